// round 11
// baseline (speedup 1.0000x reference)
#include <cuda_runtime.h>

#define BATCH 64
#define NJ 21
#define BJ (BATCH * NJ)        // 1344
#define IMG 256

// w[d] = exp(-d^2 / (2 * 2.5^2)) = exp(-d^2 / 12.5), d = 0..5
__constant__ float c_w[6] = {
    1.0f,
    0.92311634638663580f,   // exp(-0.08)
    0.72614903707369090f,   // exp(-0.32)
    0.48675225595997170f,   // exp(-0.72)
    0.27803730045319410f,   // exp(-1.28)
    0.13533528323661270f    // exp(-2.00)
};

// One block = one full (batch, joint) 256x256 map.
// 512 threads; each thread writes 16 x 256-bit stores (st.global.v8.f32,
// Blackwell 256-bit store). Lanes are 32B-contiguous -> each warp store
// covers 1024B contiguous; each unrolled step writes 16 full rows (16 KB).
// Thread 0 computes the fisheye seed for this map in double (matches jnp
// round-half-to-even exactly; avoids trig via cos(phi)=x/rho, sin(phi)=y/rho).
__global__ void __launch_bounds__(512) hm_kernel(float* __restrict__ out,
                                                 const float* __restrict__ joint) {
    __shared__ int2 s_seed;

    const unsigned bj = blockIdx.x;

    if (threadIdx.x == 0) {
        double x = (double)joint[bj * 3 + 0];
        double y = (double)joint[bj * 3 + 1];
        double z = (double)joint[bj * 3 + 2];
        double rho = sqrt(x * x + y * y);
        double theta = atan2(rho, z);
        double r = 128.0 * theta / 1.5707963267948966;  // RADIUS * theta / (pi/2)
        double cphi, sphi;
        if (rho > 0.0) { cphi = x / rho; sphi = y / rho; }
        else           { cphi = 1.0;     sphi = 0.0;     }
        int sx = (int)rint(128.0 + r * cphi);
        int sy = (int)rint(128.0 + r * sphi);
        sx = min(max(sx, 0), IMG - 1);
        sy = min(max(sy, 0), IMG - 1);
        s_seed = make_int2(sx, sy);
    }
    __syncthreads();
    const int2 s = s_seed;

    const unsigned tid = threadIdx.x;
    const unsigned x0  = (tid & 31u) << 3;      // 8 consecutive pixels per thread

    // Column weights: invariant across all 16 rows this thread touches.
    float wx[8];
#pragma unroll
    for (int k = 0; k < 8; k++) {
        int dx  = (int)(x0 + k) - s.x;
        int adx = dx < 0 ? -dx : dx;
        wx[k] = (adx <= 5) ? c_w[adx] : 0.0f;
    }

    const int    y_first = (int)(tid >> 5);     // row at k=0 (0..15); +16 per k
    float* o = out + (size_t)bj * (IMG * IMG) + (size_t)y_first * IMG + x0;

#pragma unroll
    for (int k = 0; k < 16; k++) {
        int y   = y_first + k * 16;
        int dy  = y - s.y;
        int ady = dy < 0 ? -dy : dy;
        float wy = (ady <= 5) ? c_w[ady] : 0.0f;

        float v0 = wy * wx[0], v1 = wy * wx[1], v2 = wy * wx[2], v3 = wy * wx[3];
        float v4 = wy * wx[4], v5 = wy * wx[5], v6 = wy * wx[6], v7 = wy * wx[7];

        asm volatile(
            "st.global.v8.f32 [%0], {%1, %2, %3, %4, %5, %6, %7, %8};"
            :: "l"(o + (size_t)k * (16 * IMG)),
               "f"(v0), "f"(v1), "f"(v2), "f"(v3),
               "f"(v4), "f"(v5), "f"(v6), "f"(v7)
            : "memory");
    }
}

extern "C" void kernel_launch(void* const* d_in, const int* in_sizes, int n_in,
                              void* d_out, int out_size) {
    const float* joint = (const float*)d_in[0];
    // 1344 maps, one block each, 512 threads
    hm_kernel<<<BJ, 512>>>((float*)d_out, joint);
}

// round 12
// speedup vs baseline: 1.0339x; 1.0339x over previous
#include <cuda_runtime.h>

#define BATCH 64
#define NJ 21
#define BJ (BATCH * NJ)        // 1344
#define IMG 256

// w[d] = exp(-d^2 / (2 * 2.5^2)) = exp(-d^2 / 12.5), d = 0..5
__constant__ float c_w[6] = {
    1.0f,
    0.92311634638663580f,   // exp(-0.08)
    0.72614903707369090f,   // exp(-0.32)
    0.48675225595997170f,   // exp(-0.72)
    0.27803730045319410f,   // exp(-1.28)
    0.13533528323661270f    // exp(-2.00)
};

// One block = one full (batch, joint) 256x256 map.
// 256 threads; each thread writes 32 x 256-bit stores (st.global.v8.f32) —
// the proven 32-deep store stream, now at 1024 B per warp-instruction.
// Per unrolled step the block writes 8 contiguous rows (8 KB).
// Thread 0 computes the fisheye seed for this map in double (matches jnp
// round-half-to-even exactly; avoids trig via cos(phi)=x/rho, sin(phi)=y/rho).
__global__ void __launch_bounds__(256) hm_kernel(float* __restrict__ out,
                                                 const float* __restrict__ joint) {
    __shared__ int2 s_seed;

    const unsigned bj = blockIdx.x;

    if (threadIdx.x == 0) {
        double x = (double)joint[bj * 3 + 0];
        double y = (double)joint[bj * 3 + 1];
        double z = (double)joint[bj * 3 + 2];
        double rho = sqrt(x * x + y * y);
        double theta = atan2(rho, z);
        double r = 128.0 * theta / 1.5707963267948966;  // RADIUS * theta / (pi/2)
        double cphi, sphi;
        if (rho > 0.0) { cphi = x / rho; sphi = y / rho; }
        else           { cphi = 1.0;     sphi = 0.0;     }
        int sx = (int)rint(128.0 + r * cphi);
        int sy = (int)rint(128.0 + r * sphi);
        sx = min(max(sx, 0), IMG - 1);
        sy = min(max(sy, 0), IMG - 1);
        s_seed = make_int2(sx, sy);
    }
    __syncthreads();
    const int2 s = s_seed;

    const unsigned tid = threadIdx.x;
    const unsigned x0  = (tid & 31u) << 3;      // 8 consecutive pixels per thread

    // Column weights: invariant across all 32 rows this thread touches.
    float wx[8];
#pragma unroll
    for (int k = 0; k < 8; k++) {
        int dx  = (int)(x0 + k) - s.x;
        int adx = dx < 0 ? -dx : dx;
        wx[k] = (adx <= 5) ? c_w[adx] : 0.0f;
    }

    const int y_first = (int)(tid >> 5);        // row at k=0 (0..7); +8 per k
    float* o = out + (size_t)bj * (IMG * IMG) + (size_t)y_first * IMG + x0;

#pragma unroll
    for (int k = 0; k < 32; k++) {
        int y   = y_first + k * 8;
        int dy  = y - s.y;
        int ady = dy < 0 ? -dy : dy;
        float wy = (ady <= 5) ? c_w[ady] : 0.0f;

        float v0 = wy * wx[0], v1 = wy * wx[1], v2 = wy * wx[2], v3 = wy * wx[3];
        float v4 = wy * wx[4], v5 = wy * wx[5], v6 = wy * wx[6], v7 = wy * wx[7];

        asm volatile(
            "st.global.v8.f32 [%0], {%1, %2, %3, %4, %5, %6, %7, %8};"
            :: "l"(o + (size_t)k * (8 * IMG)),
               "f"(v0), "f"(v1), "f"(v2), "f"(v3),
               "f"(v4), "f"(v5), "f"(v6), "f"(v7)
            : "memory");
    }
}

extern "C" void kernel_launch(void* const* d_in, const int* in_sizes, int n_in,
                              void* d_out, int out_size) {
    const float* joint = (const float*)d_in[0];
    // 1344 maps, one block each, 256 threads
    hm_kernel<<<BJ, 256>>>((float*)d_out, joint);
}

// round 13
// speedup vs baseline: 1.0637x; 1.0288x over previous
#include <cuda_runtime.h>

#define BATCH 64
#define NJ 21
#define BJ (BATCH * NJ)        // 1344
#define IMG 256

// w[d] = exp(-d^2 / (2 * 2.5^2)) = exp(-d^2 / 12.5), d = 0..5
__constant__ float c_w[6] = {
    1.0f,
    0.92311634638663580f,   // exp(-0.08)
    0.72614903707369090f,   // exp(-0.32)
    0.48675225595997170f,   // exp(-0.72)
    0.27803730045319410f,   // exp(-1.28)
    0.13533528323661270f    // exp(-2.00)
};

// One block = one full (batch, joint) 256x256 map.
// 512 threads, each thread writes 32 float4 (lane-contiguous per store,
// 8 KB contiguous per unrolled step). Stores use __stcg (L2 write-back,
// L1 bypass) — pure write stream never re-reads, L1 adds no value.
// Thread 0 computes the fisheye seed for this map in double (matches jnp
// round-half-to-even exactly; avoids trig via cos(phi)=x/rho, sin(phi)=y/rho).
__global__ void __launch_bounds__(512) hm_kernel(float4* __restrict__ out,
                                                 const float* __restrict__ joint) {
    __shared__ int2 s_seed;

    const unsigned bj = blockIdx.x;

    if (threadIdx.x == 0) {
        double x = (double)joint[bj * 3 + 0];
        double y = (double)joint[bj * 3 + 1];
        double z = (double)joint[bj * 3 + 2];
        double rho = sqrt(x * x + y * y);
        double theta = atan2(rho, z);
        double r = 128.0 * theta / 1.5707963267948966;  // RADIUS * theta / (pi/2)
        double cphi, sphi;
        if (rho > 0.0) { cphi = x / rho; sphi = y / rho; }
        else           { cphi = 1.0;     sphi = 0.0;     }
        int sx = (int)rint(128.0 + r * cphi);
        int sy = (int)rint(128.0 + r * sphi);
        sx = min(max(sx, 0), IMG - 1);
        sy = min(max(sy, 0), IMG - 1);
        s_seed = make_int2(sx, sy);
    }
    __syncthreads();
    const int2 s = s_seed;

    const unsigned tid = threadIdx.x;
    const unsigned x0  = (tid & 63u) << 2;      // column of this thread's float4

    // Column weights: invariant across all 32 rows this thread touches.
    float4 wx;
    {
        float* wxp = reinterpret_cast<float*>(&wx);
#pragma unroll
        for (int k = 0; k < 4; k++) {
            int dx  = (int)(x0 + k) - s.x;
            int adx = dx < 0 ? -dx : dx;
            wxp[k] = (adx <= 5) ? c_w[adx] : 0.0f;
        }
    }

    const int    y_first = (int)(tid >> 6);     // row at k=0; +8 per k
    const size_t base    = (size_t)bj * (IMG * IMG / 4) + tid;
    float4* o = out + base;

#pragma unroll
    for (int k = 0; k < 32; k++) {
        int y   = y_first + k * 8;
        int dy  = y - s.y;
        int ady = dy < 0 ? -dy : dy;
        float wy = (ady <= 5) ? c_w[ady] : 0.0f;
        __stcg(o + (size_t)k * 512,
               make_float4(wy * wx.x, wy * wx.y, wy * wx.z, wy * wx.w));
    }
}

extern "C" void kernel_launch(void* const* d_in, const int* in_sizes, int n_in,
                              void* d_out, int out_size) {
    const float* joint = (const float*)d_in[0];
    // 1344 maps, one block each, 512 threads
    hm_kernel<<<BJ, 512>>>((float4*)d_out, joint);
}